// round 6
// baseline (speedup 1.0000x reference)
#include <cuda_runtime.h>
#include <math.h>

#define NB   4        // batch / classes
#define DD   512      // feature dim
#define TPB  128      // threads per block
#define GRID 16       // compute blocks
#define CPB  32       // output columns per block (GRID*CPB = 512)
#define F4G  8        // float4 column-groups per block (CPB/4)
#define KSP  16       // k-split factor (TPB / F4G)
#define KPER 32       // k iterations per thread (DD / KSP)
#define ALPHA_IT 0.7f
#define BETA_IT  0.5f

// 16 blocks x 128 threads. Each block redundantly computes the tiny graph
// coefficients, then its own 32 output columns of the dual GEMV (float4
// weight loads, 16-way k-split) + tanh + blend.
__global__ void __launch_bounds__(TPB)
graphlearner_compute(const float* __restrict__ bt,    // (4,512)
                     const float* __restrict__ bi,    // (4,512)
                     const float* __restrict__ Wtt,   // (512,512)
                     const float* __restrict__ btt,   // (4,512)
                     const float* __restrict__ Wit,   // (512,512)
                     const float* __restrict__ bit_,  // (4,512)
                     float* __restrict__ out)         // refined (4,512)
{
    const int tid = threadIdx.x;

    __shared__ float bt_s[NB][DD];                    // 8 KB, live to end
    __shared__ float v_tt[NB][DD];                    // 8 KB
    __shared__ float v_it[NB][DD];                    // 8 KB
    // 16 KB buffer: first bi_s (4x512 floats), later the two pacc arrays
    __shared__ __align__(16) float buf[4096];
    __shared__ float raw[3][NB][NB];
    __shared__ float c_tt[NB][5];
    __shared__ float c_it[NB][5];

    float* bi_s = buf;                                // [NB][DD] view

    // ---- load bt, bi (float4, coalesced) ----
    {
        const float4* bt4 = (const float4*)bt;
        const float4* bi4 = (const float4*)bi;
        float4* bts4 = (float4*)bt_s;
        float4* bis4 = (float4*)bi_s;
        #pragma unroll
        for (int i = tid; i < NB * DD / 4; i += TPB) {
            bts4[i] = bt4[i];
            bis4[i] = bi4[i];
        }
    }
    __syncthreads();

    // ---- 48 dot products (3 gram matrices), float4 LDS, 4 warps ----
    {
        const int warp = tid >> 5, lane = tid & 31;
        for (int q = warp; q < 48; q += 4) {
            const int mat = q >> 4, i = (q & 15) >> 2, j = q & 3;
            const float4* a4 = (const float4*)((mat == 2) ? (bi_s + i * DD)
                                                          : bt_s[i]);
            const float4* c4 = (const float4*)((mat == 0) ? bt_s[j]
                                                          : (bi_s + j * DD));
            float s = 0.f;
            #pragma unroll
            for (int jj = 0; jj < 4; jj++) {
                float4 av = a4[lane + 32 * jj];
                float4 cv = c4[lane + 32 * jj];
                s = fmaf(av.x, cv.x, s);
                s = fmaf(av.y, cv.y, s);
                s = fmaf(av.z, cv.z, s);
                s = fmaf(av.w, cv.w, s);
            }
            #pragma unroll
            for (int off = 16; off > 0; off >>= 1)
                s += __shfl_down_sync(0xffffffffu, s, off);
            if (lane == 0) raw[mat][i][j] = s;
        }
    }
    __syncthreads();

    // ---- 8 tiny graphs: row-0 normalized-adjacency coefficients ----
    if (tid < 8) {
        const int b = tid & 3;
        const bool is_it = tid >= 4;
        float nt[NB], ni[NB];
        #pragma unroll
        for (int i = 0; i < NB; i++) {
            nt[i] = fmaxf(sqrtf(raw[0][i][i]), 1e-12f);
            ni[i] = fmaxf(sqrtf(raw[2][i][i]), 1e-12f);
        }
        float e[5][5];
        if (!is_it) {
            e[0][0] = raw[0][b][b] / (nt[b] * nt[b]);
            #pragma unroll
            for (int m = 1; m < 5; m++) {
                e[0][m] = raw[0][b][m - 1] / (nt[b] * nt[m - 1]);
                e[m][0] = raw[0][m - 1][b] / (nt[m - 1] * nt[b]);
            }
            #pragma unroll
            for (int n = 1; n < 5; n++)
                #pragma unroll
                for (int m = 1; m < 5; m++)
                    e[n][m] = raw[0][n - 1][m - 1] / (nt[n - 1] * nt[m - 1]);
        } else {
            e[0][0] = raw[0][b][b] / (nt[b] * nt[b]);
            #pragma unroll
            for (int m = 1; m < 5; m++) {
                e[0][m] = raw[1][b][m - 1] / (nt[b] * ni[m - 1]);
                e[m][0] = e[0][m];
            }
            #pragma unroll
            for (int n = 1; n < 5; n++)
                #pragma unroll
                for (int m = 1; m < 5; m++)
                    e[n][m] = raw[2][n - 1][m - 1] / (ni[n - 1] * ni[m - 1]);
        }
        float adj[5][5], deg[5];
        #pragma unroll
        for (int n = 0; n < 5; n++) {
            deg[n] = 0.f;
            #pragma unroll
            for (int m = 0; m < 5; m++) {
                adj[n][m] = fmaxf(e[n][m], 0.f) + ((n == m) ? 1.f : 0.f);
                deg[n] += adj[n][m];
            }
        }
        float dinv[5];
        #pragma unroll
        for (int n = 0; n < 5; n++)
            dinv[n] = (deg[n] > 0.f) ? (1.f / sqrtf(deg[n])) : 0.f;
        float* cc = is_it ? c_it[b] : c_tt[b];
        #pragma unroll
        for (int m = 0; m < 5; m++)
            cc[m] = dinv[0] * adj[0][m] * dinv[m];
    }
    __syncthreads();

    // ---- combined vectors v[b] = c[b,0]*node0 + sum_j c[b,j+1]*node_j ----
    #pragma unroll
    for (int i = tid; i < NB * DD; i += TPB) {
        const int b = i >> 9, k = i & (DD - 1);
        float vt = c_tt[b][0] * bt_s[b][k];
        float vi = c_it[b][0] * bt_s[b][k];
        #pragma unroll
        for (int j = 0; j < 4; j++) {
            vt = fmaf(c_tt[b][j + 1], bt_s[j][k],       vt);
            vi = fmaf(c_it[b][j + 1], bi_s[j * DD + k], vi);
        }
        v_tt[b][k] = vt;
        v_it[b][k] = vi;
    }
    __syncthreads();   // also retires all bi_s reads before buf is reused

    // ---- dual GEMV: float4 weight loads, 16-way k-split ----
    float4* pacc_tt = (float4*)buf;
    float4* pacc_it = pacc_tt + KSP * F4G * NB;

    const int f4g = tid & (F4G - 1);
    const int ksp = tid >> 3;                  // 0..15
    const int d0  = blockIdx.x * CPB + f4g * 4;

    float4 att[NB], ait[NB];
    #pragma unroll
    for (int b = 0; b < NB; b++) {
        att[b] = make_float4(0.f, 0.f, 0.f, 0.f);
        ait[b] = make_float4(0.f, 0.f, 0.f, 0.f);
    }
    const int kbase = ksp * KPER;
    #pragma unroll 8
    for (int kk = 0; kk < KPER; kk++) {
        const int k = kbase + kk;
        const float4 wt = *(const float4*)(Wtt + (size_t)k * DD + d0);
        const float4 wi = *(const float4*)(Wit + (size_t)k * DD + d0);
        #pragma unroll
        for (int b = 0; b < NB; b++) {
            const float vt = v_tt[b][k];
            const float vi = v_it[b][k];
            att[b].x = fmaf(vt, wt.x, att[b].x);
            att[b].y = fmaf(vt, wt.y, att[b].y);
            att[b].z = fmaf(vt, wt.z, att[b].z);
            att[b].w = fmaf(vt, wt.w, att[b].w);
            ait[b].x = fmaf(vi, wi.x, ait[b].x);
            ait[b].y = fmaf(vi, wi.y, ait[b].y);
            ait[b].z = fmaf(vi, wi.z, ait[b].z);
            ait[b].w = fmaf(vi, wi.w, ait[b].w);
        }
    }
    #pragma unroll
    for (int b = 0; b < NB; b++) {
        pacc_tt[(ksp * F4G + f4g) * NB + b] = att[b];
        pacc_it[(ksp * F4G + f4g) * NB + b] = ait[b];
    }
    __syncthreads();

    // ---- reduction + tanh + blend: one thread per (d_local, b) ----
    {
        const int d_local = tid & (CPB - 1);   // 0..31
        const int b       = tid >> 5;          // 0..3
        const int fg      = d_local >> 2;
        const int comp    = d_local & 3;
        const int d       = blockIdx.x * CPB + d_local;

        const float* pt = (const float*)pacc_tt;
        const float* pi = (const float*)pacc_it;
        float stt = btt[b * DD + d];
        float sit = bit_[b * DD + d];
        #pragma unroll
        for (int s = 0; s < KSP; s++) {
            const int idx = ((s * F4G + fg) * NB + b) * 4 + comp;
            stt += pt[idx];
            sit += pi[idx];
        }
        const float g = ALPHA_IT * tanhf(stt) + (1.f - ALPHA_IT) * tanhf(sit);
        out[b * DD + d] = BETA_IT * bt_s[b][d] + (1.f - BETA_IT) * g;
    }
}

extern "C" void kernel_launch(void* const* d_in, const int* in_sizes, int n_in,
                              void* d_out, int out_size) {
    const float* bt   = (const float*)d_in[0];
    const float* bi   = (const float*)d_in[1];
    const float* img  = (const float*)d_in[2];
    const float* Wtt  = (const float*)d_in[3];
    const float* btt  = (const float*)d_in[4];
    const float* Wit  = (const float*)d_in[5];
    const float* bit_ = (const float*)d_in[6];
    float* out = (float*)d_out;

    // One-time creation on the first (uncaptured) correctness call.
    // No device memory is allocated; the captured graph is identical per call.
    static cudaStream_t s_copy = []() {
        cudaStream_t s;
        cudaStreamCreateWithFlags(&s, cudaStreamNonBlocking);
        return s;
    }();
    static cudaEvent_t ev_fork = []() {
        cudaEvent_t e;
        cudaEventCreateWithFlags(&e, cudaEventDisableTiming);
        return e;
    }();
    static cudaEvent_t ev_join = []() {
        cudaEvent_t e;
        cudaEventCreateWithFlags(&e, cudaEventDisableTiming);
        return e;
    }();

    // Fork: copy branch runs concurrently with the compute kernel.
    cudaEventRecord(ev_fork, 0);
    cudaStreamWaitEvent(s_copy, ev_fork, 0);

    // bulk passthrough: img_feature (84 MB) -> out + 2048 (driver D2D copy)
    const size_t n_img_bytes = (size_t)in_sizes[2] * sizeof(float);
    cudaMemcpyAsync(out + NB * DD, img, n_img_bytes,
                    cudaMemcpyDeviceToDevice, s_copy);

    // tiny graph + dual GEMV -> refined (first 2048 floats of out)
    graphlearner_compute<<<GRID, TPB>>>(bt, bi, Wtt, btt, Wit, bit_, out);

    // Join: main stream waits for the copy branch.
    cudaEventRecord(ev_join, s_copy);
    cudaStreamWaitEvent(0, ev_join, 0);
}

// round 7
// speedup vs baseline: 1.4037x; 1.4037x over previous
#include <cuda_runtime.h>
#include <math.h>

#define NB   4        // batch / classes
#define DD   512      // feature dim
#define TPB  128      // threads per block
#define GRID 64       // compute blocks
#define CPB  8        // output columns per block (GRID*CPB = 512)
#define NSPL 32       // k-splits (tid>>2)
#define KPER 16       // k per thread (DD/NSPL)
#define PROW 68       // padded pacc row (floats) per split
#define ALPHA_IT 0.7f
#define BETA_IT  0.5f

// 64 blocks x 128 threads. Each block redundantly computes the tiny graph
// coefficients, then its 8 output columns of the dual GEMV. GEMV split:
// tid -> (mat, colgroup, ksplit); each thread does 16 independent LDG.128
// with only 4 float4 accumulators, so the full load set is in flight.
__global__ void __launch_bounds__(TPB)
graphlearner_compute(const float* __restrict__ bt,    // (4,512)
                     const float* __restrict__ bi,    // (4,512)
                     const float* __restrict__ Wtt,   // (512,512)
                     const float* __restrict__ btt,   // (4,512)
                     const float* __restrict__ Wit,   // (512,512)
                     const float* __restrict__ bit_,  // (4,512)
                     float* __restrict__ out)         // refined (4,512)
{
    const int tid = threadIdx.x;

    __shared__ float bt_s[NB][DD];                    // 8 KB, live to end
    __shared__ float v_tt[NB][DD];                    // 8 KB
    __shared__ float v_it[NB][DD];                    // 8 KB
    // 16 KB buffer: first bi_s (4x512 floats), later pacc (32 x 68 floats)
    __shared__ __align__(16) float buf[4096];
    __shared__ float raw[3][NB][NB];
    __shared__ float c_tt[NB][5];
    __shared__ float c_it[NB][5];
    __shared__ float sums[2][NB][CPB];

    float* bi_s = buf;                                // [NB][DD] view

    // ---- load bt, bi (float4, coalesced) ----
    {
        const float4* bt4 = (const float4*)bt;
        const float4* bi4 = (const float4*)bi;
        float4* bts4 = (float4*)bt_s;
        float4* bis4 = (float4*)bi_s;
        #pragma unroll
        for (int i = tid; i < NB * DD / 4; i += TPB) {
            bts4[i] = bt4[i];
            bis4[i] = bi4[i];
        }
    }
    __syncthreads();

    // ---- 48 dot products (3 gram matrices), float4 LDS, 4 warps ----
    {
        const int warp = tid >> 5, lane = tid & 31;
        for (int q = warp; q < 48; q += 4) {
            const int mat = q >> 4, i = (q & 15) >> 2, j = q & 3;
            const float4* a4 = (const float4*)((mat == 2) ? (bi_s + i * DD)
                                                          : bt_s[i]);
            const float4* c4 = (const float4*)((mat == 0) ? bt_s[j]
                                                          : (bi_s + j * DD));
            float s = 0.f;
            #pragma unroll
            for (int jj = 0; jj < 4; jj++) {
                float4 av = a4[lane + 32 * jj];
                float4 cv = c4[lane + 32 * jj];
                s = fmaf(av.x, cv.x, s);
                s = fmaf(av.y, cv.y, s);
                s = fmaf(av.z, cv.z, s);
                s = fmaf(av.w, cv.w, s);
            }
            #pragma unroll
            for (int off = 16; off > 0; off >>= 1)
                s += __shfl_down_sync(0xffffffffu, s, off);
            if (lane == 0) raw[mat][i][j] = s;
        }
    }
    __syncthreads();

    // ---- 8 tiny graphs: row-0 normalized-adjacency coefficients ----
    if (tid < 8) {
        const int b = tid & 3;
        const bool is_it = tid >= 4;
        float nt[NB], ni[NB];
        #pragma unroll
        for (int i = 0; i < NB; i++) {
            nt[i] = fmaxf(sqrtf(raw[0][i][i]), 1e-12f);
            ni[i] = fmaxf(sqrtf(raw[2][i][i]), 1e-12f);
        }
        float e[5][5];
        if (!is_it) {
            e[0][0] = raw[0][b][b] / (nt[b] * nt[b]);
            #pragma unroll
            for (int m = 1; m < 5; m++) {
                e[0][m] = raw[0][b][m - 1] / (nt[b] * nt[m - 1]);
                e[m][0] = raw[0][m - 1][b] / (nt[m - 1] * nt[b]);
            }
            #pragma unroll
            for (int n = 1; n < 5; n++)
                #pragma unroll
                for (int m = 1; m < 5; m++)
                    e[n][m] = raw[0][n - 1][m - 1] / (nt[n - 1] * nt[m - 1]);
        } else {
            e[0][0] = raw[0][b][b] / (nt[b] * nt[b]);
            #pragma unroll
            for (int m = 1; m < 5; m++) {
                e[0][m] = raw[1][b][m - 1] / (nt[b] * ni[m - 1]);
                e[m][0] = e[0][m];
            }
            #pragma unroll
            for (int n = 1; n < 5; n++)
                #pragma unroll
                for (int m = 1; m < 5; m++)
                    e[n][m] = raw[2][n - 1][m - 1] / (ni[n - 1] * ni[m - 1]);
        }
        float adj[5][5], deg[5];
        #pragma unroll
        for (int n = 0; n < 5; n++) {
            deg[n] = 0.f;
            #pragma unroll
            for (int m = 0; m < 5; m++) {
                adj[n][m] = fmaxf(e[n][m], 0.f) + ((n == m) ? 1.f : 0.f);
                deg[n] += adj[n][m];
            }
        }
        float dinv[5];
        #pragma unroll
        for (int n = 0; n < 5; n++)
            dinv[n] = (deg[n] > 0.f) ? (1.f / sqrtf(deg[n])) : 0.f;
        float* cc = is_it ? c_it[b] : c_tt[b];
        #pragma unroll
        for (int m = 0; m < 5; m++)
            cc[m] = dinv[0] * adj[0][m] * dinv[m];
    }
    __syncthreads();

    // ---- combined vectors v[b] = c[b,0]*node0 + sum_j c[b,j+1]*node_j ----
    #pragma unroll
    for (int i = tid; i < NB * DD; i += TPB) {
        const int b = i >> 9, k = i & (DD - 1);
        float vt = c_tt[b][0] * bt_s[b][k];
        float vi = c_it[b][0] * bt_s[b][k];
        #pragma unroll
        for (int j = 0; j < 4; j++) {
            vt = fmaf(c_tt[b][j + 1], bt_s[j][k],       vt);
            vi = fmaf(c_it[b][j + 1], bi_s[j * DD + k], vi);
        }
        v_tt[b][k] = vt;
        v_it[b][k] = vi;
    }
    __syncthreads();   // retires all bi_s reads before buf is reused as pacc

    // ---- dual GEMV, one matrix per thread ----
    // tid -> mat (bit0), colgroup g (bit1), ksplit s (bits 2..6)
    {
        const int mat = tid & 1;
        const int g   = (tid >> 1) & 1;
        const int s   = tid >> 2;                 // 0..31
        const int d0  = blockIdx.x * CPB + g * 4;
        const float* __restrict__ W = mat ? Wit : Wtt;
        const float (*__restrict__ vv)[DD] = mat ? v_it : v_tt;

        float4 acc[NB];
        #pragma unroll
        for (int b = 0; b < NB; b++)
            acc[b] = make_float4(0.f, 0.f, 0.f, 0.f);

        const int kbase = s * KPER;
        #pragma unroll
        for (int kk = 0; kk < KPER; kk++) {
            const int k = kbase + kk;
            const float4 w = *(const float4*)(W + (size_t)k * DD + d0);
            #pragma unroll
            for (int b = 0; b < NB; b++) {
                const float v = vv[b][k];
                acc[b].x = fmaf(v, w.x, acc[b].x);
                acc[b].y = fmaf(v, w.y, acc[b].y);
                acc[b].z = fmaf(v, w.z, acc[b].z);
                acc[b].w = fmaf(v, w.w, acc[b].w);
            }
        }
        // pacc[s] row: 68 floats; offset (g*2+mat)*16 + b*4
        float* prow = buf + s * PROW + (g * 2 + mat) * 16;
        #pragma unroll
        for (int b = 0; b < NB; b++)
            *(float4*)(prow + b * 4) = acc[b];
    }
    __syncthreads();

    // ---- reduction over 32 k-splits: 64 threads, one per (col,b,mat) ----
    if (tid < 64) {
        const int col  = tid & 7;          // 0..7
        const int b    = (tid >> 3) & 3;   // 0..3
        const int mat  = tid >> 5;         // 0..1
        const int g    = col >> 2;
        const int comp = col & 3;
        const float* base = buf + (g * 2 + mat) * 16 + b * 4 + comp;
        float sum = 0.f;
        #pragma unroll
        for (int s = 0; s < NSPL; s++)
            sum += base[s * PROW];
        sums[mat][b][col] = sum;
    }
    __syncthreads();

    // ---- tanh + blend: 32 threads, one per (b, col) ----
    if (tid < 32) {
        const int col = tid & 7;
        const int b   = tid >> 3;
        const int d   = blockIdx.x * CPB + col;
        const float stt = sums[0][b][col] + btt[b * DD + d];
        const float sit = sums[1][b][col] + bit_[b * DD + d];
        const float g = ALPHA_IT * tanhf(stt) + (1.f - ALPHA_IT) * tanhf(sit);
        out[b * DD + d] = BETA_IT * bt_s[b][d] + (1.f - BETA_IT) * g;
    }
}

extern "C" void kernel_launch(void* const* d_in, const int* in_sizes, int n_in,
                              void* d_out, int out_size) {
    const float* bt   = (const float*)d_in[0];
    const float* bi   = (const float*)d_in[1];
    const float* img  = (const float*)d_in[2];
    const float* Wtt  = (const float*)d_in[3];
    const float* btt  = (const float*)d_in[4];
    const float* Wit  = (const float*)d_in[5];
    const float* bit_ = (const float*)d_in[6];
    float* out = (float*)d_out;

    // 1) tiny graph + dual GEMV -> refined (first 2048 floats of out)
    graphlearner_compute<<<GRID, TPB>>>(bt, bi, Wtt, btt, Wit, bit_, out);

    // 2) bulk passthrough: img_feature (84 MB) -> out + 2048 via the
    //    driver-optimized D2D copy (graph-capturable, allocation-free)
    const size_t n_img_bytes = (size_t)in_sizes[2] * sizeof(float);
    cudaMemcpyAsync(out + NB * DD, img, n_img_bytes, cudaMemcpyDeviceToDevice);
}

// round 8
// speedup vs baseline: 1.5553x; 1.1080x over previous
#include <cuda_runtime.h>
#include <math.h>

#define NB   4        // batch / classes
#define DD   512      // feature dim
#define TPB  256
#define GRID 64       // compute blocks
#define CPB  8        // output columns per block
#define ALPHA_IT 0.7f
#define BETA_IT  0.5f

// 64 blocks x 256 threads, short-critical-path version.
// Key idea: per-node GEMV partials u_tt[m], u_itb[m], u_iti[m] do NOT depend
// on the graph coefficients, so the DRAM-heavy GEMV starts immediately after
// the feature load; gram dots follow in the same warps; the tiny graph and
// the split-reduction run in parallel; coefficients are applied at the end.
__global__ void __launch_bounds__(TPB)
graphlearner_compute(const float* __restrict__ bt,    // (4,512)
                     const float* __restrict__ bi,    // (4,512)
                     const float* __restrict__ Wtt,   // (512,512)
                     const float* __restrict__ btt,   // (4,512)
                     const float* __restrict__ Wit,   // (512,512)
                     const float* __restrict__ bit_,  // (4,512)
                     float* __restrict__ out)         // refined (4,512)
{
    const int tid  = threadIdx.x;
    const int warp = tid >> 5, lane = tid & 31;

    __shared__ float bt_s[NB][DD];                       // 8 KB
    __shared__ float bi_s[NB][DD];                       // 8 KB
    __shared__ __align__(16) float pacc_tt[64][32];      // 8 KB
    __shared__ __align__(16) float pacc_it[64][64];      // 16 KB
    __shared__ float raw[3][NB][NB];
    __shared__ float c_tt[NB][5], c_it[NB][5];
    __shared__ float sums[96];

    // ---- A: load features (float4) ----
    {
        const float4* bt4 = (const float4*)bt;
        const float4* bi4 = (const float4*)bi;
        #pragma unroll
        for (int i = tid; i < NB * DD / 4; i += TPB) {
            ((float4*)bt_s)[i] = bt4[i];
            ((float4*)bi_s)[i] = bi4[i];
        }
    }
    __syncthreads();

    // ---- B: per-node GEMV partials (no dependency on coefficients) ----
    // tid<128: Wtt -> u_tt[m];  tid>=128: Wit -> u_itb[m] (x bt), u_iti[m] (x bi)
    {
        const int g   = tid & 1;                 // column group (4 cols)
        const int s   = (tid >> 1) & 63;         // k-split 0..63
        const int mat = tid >> 7;                // 0 = tt, 1 = it (warp-uniform)
        const int d0  = blockIdx.x * CPB + g * 4;
        const float* __restrict__ W = mat ? Wit : Wtt;

        float4 accB[NB], accI[NB];
        #pragma unroll
        for (int m = 0; m < NB; m++) {
            accB[m] = make_float4(0.f, 0.f, 0.f, 0.f);
            accI[m] = make_float4(0.f, 0.f, 0.f, 0.f);
        }
        #pragma unroll
        for (int kk = 0; kk < 8; kk++) {
            const int k = kk * 64 + s;           // conflict-free LDS mapping
            const float4 w = *(const float4*)(W + (size_t)k * DD + d0);
            #pragma unroll
            for (int m = 0; m < NB; m++) {
                const float bm = bt_s[m][k];
                accB[m].x = fmaf(bm, w.x, accB[m].x);
                accB[m].y = fmaf(bm, w.y, accB[m].y);
                accB[m].z = fmaf(bm, w.z, accB[m].z);
                accB[m].w = fmaf(bm, w.w, accB[m].w);
            }
            if (mat) {
                #pragma unroll
                for (int m = 0; m < NB; m++) {
                    const float im = bi_s[m][k];
                    accI[m].x = fmaf(im, w.x, accI[m].x);
                    accI[m].y = fmaf(im, w.y, accI[m].y);
                    accI[m].z = fmaf(im, w.z, accI[m].z);
                    accI[m].w = fmaf(im, w.w, accI[m].w);
                }
            }
        }
        if (mat == 0) {
            float4* row = (float4*)&pacc_tt[s][g * 16];
            #pragma unroll
            for (int m = 0; m < NB; m++) row[m] = accB[m];
        } else {
            float4* rowB = (float4*)&pacc_it[s][g * 16];
            float4* rowI = (float4*)&pacc_it[s][32 + g * 16];
            #pragma unroll
            for (int m = 0; m < NB; m++) { rowB[m] = accB[m]; rowI[m] = accI[m]; }
        }
    }

    // ---- C: gram dots, batched 4 per warp-pass (12 groups over 8 warps) ----
    {
        #pragma unroll
        for (int pass = 0; pass < 2; pass++) {
            if (pass == 1 && warp >= 4) break;
            const int G   = (pass == 0) ? warp : 8 + warp;   // 0..11
            const int mat = G >> 2, i = G & 3;
            const float4* a4 = (const float4*)((mat == 2) ? bi_s[i] : bt_s[i]);
            const float4* cb = (const float4*)((mat == 0) ? &bt_s[0][0]
                                                          : &bi_s[0][0]);
            float a0 = 0.f, a1 = 0.f, a2 = 0.f, a3 = 0.f;
            #pragma unroll
            for (int ch = 0; ch < 4; ch++) {
                const int o = lane + 32 * ch;
                const float4 av = a4[o];
                const float4 c0 = cb[0 * 128 + o];
                const float4 c1 = cb[1 * 128 + o];
                const float4 c2 = cb[2 * 128 + o];
                const float4 c3 = cb[3 * 128 + o];
                a0 = fmaf(av.x, c0.x, fmaf(av.y, c0.y, fmaf(av.z, c0.z, fmaf(av.w, c0.w, a0))));
                a1 = fmaf(av.x, c1.x, fmaf(av.y, c1.y, fmaf(av.z, c1.z, fmaf(av.w, c1.w, a1))));
                a2 = fmaf(av.x, c2.x, fmaf(av.y, c2.y, fmaf(av.z, c2.z, fmaf(av.w, c2.w, a2))));
                a3 = fmaf(av.x, c3.x, fmaf(av.y, c3.y, fmaf(av.z, c3.z, fmaf(av.w, c3.w, a3))));
            }
            #pragma unroll
            for (int off = 16; off > 0; off >>= 1) {
                a0 += __shfl_down_sync(0xffffffffu, a0, off);
                a1 += __shfl_down_sync(0xffffffffu, a1, off);
                a2 += __shfl_down_sync(0xffffffffu, a2, off);
                a3 += __shfl_down_sync(0xffffffffu, a3, off);
            }
            if (lane == 0) {
                raw[mat][i][0] = a0; raw[mat][i][1] = a1;
                raw[mat][i][2] = a2; raw[mat][i][3] = a3;
            }
        }
    }
    __syncthreads();

    // ---- D (parallel): split-reduction (warps 0-2) + tiny graph (warp 7) ----
    if (tid < 32) {
        float s0 = 0.f, s1 = 0.f, s2 = 0.f, s3 = 0.f;
        #pragma unroll
        for (int s = 0; s < 64; s += 4) {
            s0 += pacc_tt[s][tid];     s1 += pacc_tt[s + 1][tid];
            s2 += pacc_tt[s + 2][tid]; s3 += pacc_tt[s + 3][tid];
        }
        sums[tid] = (s0 + s1) + (s2 + s3);
    } else if (tid < 96) {
        const int idx = tid - 32;
        float s0 = 0.f, s1 = 0.f, s2 = 0.f, s3 = 0.f;
        #pragma unroll
        for (int s = 0; s < 64; s += 4) {
            s0 += pacc_it[s][idx];     s1 += pacc_it[s + 1][idx];
            s2 += pacc_it[s + 2][idx]; s3 += pacc_it[s + 3][idx];
        }
        sums[32 + idx] = (s0 + s1) + (s2 + s3);
    } else if (tid >= 224 && tid < 232) {
        const int b = tid & 3;
        const bool is_it = (tid & 4) != 0;
        float rnt[NB], rni[NB];
        #pragma unroll
        for (int i = 0; i < NB; i++) {
            rnt[i] = rsqrtf(fmaxf(raw[0][i][i], 1e-24f));  // == 1/max(sqrt,1e-12)
            rni[i] = rsqrtf(fmaxf(raw[2][i][i], 1e-24f));
        }
        float e[5][5];
        if (!is_it) {
            e[0][0] = raw[0][b][b] * rnt[b] * rnt[b];
            #pragma unroll
            for (int m = 1; m < 5; m++) {
                e[0][m] = raw[0][b][m - 1] * rnt[b] * rnt[m - 1];
                e[m][0] = raw[0][m - 1][b] * rnt[m - 1] * rnt[b];
            }
            #pragma unroll
            for (int n = 1; n < 5; n++)
                #pragma unroll
                for (int m = 1; m < 5; m++)
                    e[n][m] = raw[0][n - 1][m - 1] * rnt[n - 1] * rnt[m - 1];
        } else {
            e[0][0] = raw[0][b][b] * rnt[b] * rnt[b];
            #pragma unroll
            for (int m = 1; m < 5; m++) {
                e[0][m] = raw[1][b][m - 1] * rnt[b] * rni[m - 1];
                e[m][0] = e[0][m];
            }
            #pragma unroll
            for (int n = 1; n < 5; n++)
                #pragma unroll
                for (int m = 1; m < 5; m++)
                    e[n][m] = raw[2][n - 1][m - 1] * rni[n - 1] * rni[m - 1];
        }
        float adj[5][5], deg[5];
        #pragma unroll
        for (int n = 0; n < 5; n++) {
            deg[n] = 0.f;
            #pragma unroll
            for (int m = 0; m < 5; m++) {
                adj[n][m] = fmaxf(e[n][m], 0.f) + ((n == m) ? 1.f : 0.f);
                deg[n] += adj[n][m];
            }
        }
        float dinv[5];
        #pragma unroll
        for (int n = 0; n < 5; n++)
            dinv[n] = rsqrtf(deg[n]);            // deg >= 1 always (diag +1)
        float* cc = is_it ? c_it[b] : c_tt[b];
        #pragma unroll
        for (int m = 0; m < 5; m++)
            cc[m] = dinv[0] * adj[0][m] * dinv[m];
    }
    __syncthreads();

    // ---- E: combine coefficients + bias + tanh + blend (32 threads) ----
    if (tid < 32) {
        const int col = tid & 7;
        const int b   = tid >> 3;
        const int g   = col >> 2, c = col & 3;
        const int d   = blockIdx.x * CPB + col;
        const int o   = g * 16 + c;

        float att = c_tt[b][0] * sums[o + b * 4];         // self node = bt[b]
        float ait = c_it[b][0] * sums[32 + o + b * 4];    // self node via Wit
        #pragma unroll
        for (int j = 0; j < 4; j++) {
            att = fmaf(c_tt[b][j + 1], sums[o + j * 4],      att);
            ait = fmaf(c_it[b][j + 1], sums[64 + o + j * 4], ait);
        }
        const float stt = att + btt[b * DD + d];
        const float sit = ait + bit_[b * DD + d];
        const float gg = ALPHA_IT * tanhf(stt) + (1.f - ALPHA_IT) * tanhf(sit);
        out[b * DD + d] = BETA_IT * bt_s[b][d] + (1.f - BETA_IT) * gg;
    }
}

extern "C" void kernel_launch(void* const* d_in, const int* in_sizes, int n_in,
                              void* d_out, int out_size) {
    const float* bt   = (const float*)d_in[0];
    const float* bi   = (const float*)d_in[1];
    const float* img  = (const float*)d_in[2];
    const float* Wtt  = (const float*)d_in[3];
    const float* btt  = (const float*)d_in[4];
    const float* Wit  = (const float*)d_in[5];
    const float* bit_ = (const float*)d_in[6];
    float* out = (float*)d_out;

    // 1) tiny graph + dual GEMV -> refined (first 2048 floats of out)
    graphlearner_compute<<<GRID, TPB>>>(bt, bi, Wtt, btt, Wit, bit_, out);

    // 2) bulk passthrough: img_feature (84 MB) -> out + 2048 via the
    //    driver-optimized D2D copy (graph-capturable, allocation-free)
    const size_t n_img_bytes = (size_t)in_sizes[2] * sizeof(float);
    cudaMemcpyAsync(out + NB * DD, img, n_img_bytes, cudaMemcpyDeviceToDevice);
}

// round 9
// speedup vs baseline: 1.8606x; 1.1963x over previous
#include <cuda_runtime.h>
#include <math.h>

#define NB    4       // batch / classes
#define DD    512     // feature dim
#define TPB   256
#define NCOMP 64      // compute blocks (8 output columns each)
#define NCOPY 512     // copy blocks (exactly 10240 float4 each, no tail)
#define CPB   8
#define ALPHA_IT 0.7f
#define BETA_IT  0.5f

// Fused single kernel:
//   blocks 0..63    : graph coefficients + dual GEMV -> refined (out[0:2048])
//   blocks 64..575  : stream img_feature -> out+2048, contiguous chunks,
//                     8 independent float4 loads in flight (plain ld/st).
// 576 blocks, 4 blocks/SM (launch_bounds), single wave on 148 SMs.
__global__ void __launch_bounds__(TPB, 4)
graphlearner_fused(const float* __restrict__ bt,    // (4,512)
                   const float* __restrict__ bi,    // (4,512)
                   const float* __restrict__ img,   // (40960,512)
                   const float* __restrict__ Wtt,   // (512,512)
                   const float* __restrict__ btt,   // (4,512)
                   const float* __restrict__ Wit,   // (512,512)
                   const float* __restrict__ bit_,  // (4,512)
                   float* __restrict__ out)
{
    const int tid = threadIdx.x;

    // ---------------- copy blocks ------------------------------------------
    if (blockIdx.x >= NCOMP) {
        const float4* __restrict__ src = (const float4*)img;
        float4* __restrict__ dst = (float4*)(out + NB * DD);
        const long long start = (long long)(blockIdx.x - NCOMP) * 10240;
        long long i = start + tid;
        #pragma unroll 1
        for (int it = 0; it < 5; it++, i += 8 * TPB) {
            float4 a0 = src[i];
            float4 a1 = src[i + 1 * TPB];
            float4 a2 = src[i + 2 * TPB];
            float4 a3 = src[i + 3 * TPB];
            float4 a4 = src[i + 4 * TPB];
            float4 a5 = src[i + 5 * TPB];
            float4 a6 = src[i + 6 * TPB];
            float4 a7 = src[i + 7 * TPB];
            dst[i]           = a0;
            dst[i + 1 * TPB] = a1;
            dst[i + 2 * TPB] = a2;
            dst[i + 3 * TPB] = a3;
            dst[i + 4 * TPB] = a4;
            dst[i + 5 * TPB] = a5;
            dst[i + 6 * TPB] = a6;
            dst[i + 7 * TPB] = a7;
        }
        return;
    }

    // ---------------- compute blocks (verified R8 path) --------------------
    const int warp = tid >> 5, lane = tid & 31;

    __shared__ float bt_s[NB][DD];                       // 8 KB
    __shared__ float bi_s[NB][DD];                       // 8 KB
    __shared__ __align__(16) float pacc_tt[64][32];      // 8 KB
    __shared__ __align__(16) float pacc_it[64][64];      // 16 KB
    __shared__ float raw[3][NB][NB];
    __shared__ float c_tt[NB][5], c_it[NB][5];
    __shared__ float sums[96];

    // ---- A: load features (float4) ----
    {
        const float4* bt4 = (const float4*)bt;
        const float4* bi4 = (const float4*)bi;
        #pragma unroll
        for (int i = tid; i < NB * DD / 4; i += TPB) {
            ((float4*)bt_s)[i] = bt4[i];
            ((float4*)bi_s)[i] = bi4[i];
        }
    }
    __syncthreads();

    // ---- B: per-node GEMV partials (no dependency on coefficients) ----
    {
        const int g   = tid & 1;
        const int s   = (tid >> 1) & 63;
        const int mat = tid >> 7;
        const int d0  = blockIdx.x * CPB + g * 4;
        const float* __restrict__ W = mat ? Wit : Wtt;

        float4 accB[NB], accI[NB];
        #pragma unroll
        for (int m = 0; m < NB; m++) {
            accB[m] = make_float4(0.f, 0.f, 0.f, 0.f);
            accI[m] = make_float4(0.f, 0.f, 0.f, 0.f);
        }
        #pragma unroll
        for (int kk = 0; kk < 8; kk++) {
            const int k = kk * 64 + s;
            const float4 w = *(const float4*)(W + (size_t)k * DD + d0);
            #pragma unroll
            for (int m = 0; m < NB; m++) {
                const float bm = bt_s[m][k];
                accB[m].x = fmaf(bm, w.x, accB[m].x);
                accB[m].y = fmaf(bm, w.y, accB[m].y);
                accB[m].z = fmaf(bm, w.z, accB[m].z);
                accB[m].w = fmaf(bm, w.w, accB[m].w);
            }
            if (mat) {
                #pragma unroll
                for (int m = 0; m < NB; m++) {
                    const float im = bi_s[m][k];
                    accI[m].x = fmaf(im, w.x, accI[m].x);
                    accI[m].y = fmaf(im, w.y, accI[m].y);
                    accI[m].z = fmaf(im, w.z, accI[m].z);
                    accI[m].w = fmaf(im, w.w, accI[m].w);
                }
            }
        }
        if (mat == 0) {
            float4* row = (float4*)&pacc_tt[s][g * 16];
            #pragma unroll
            for (int m = 0; m < NB; m++) row[m] = accB[m];
        } else {
            float4* rowB = (float4*)&pacc_it[s][g * 16];
            float4* rowI = (float4*)&pacc_it[s][32 + g * 16];
            #pragma unroll
            for (int m = 0; m < NB; m++) { rowB[m] = accB[m]; rowI[m] = accI[m]; }
        }
    }

    // ---- C: gram dots, batched 4 per warp-pass ----
    {
        #pragma unroll
        for (int pass = 0; pass < 2; pass++) {
            if (pass == 1 && warp >= 4) break;
            const int G   = (pass == 0) ? warp : 8 + warp;
            const int mat = G >> 2, i = G & 3;
            const float4* a4 = (const float4*)((mat == 2) ? bi_s[i] : bt_s[i]);
            const float4* cb = (const float4*)((mat == 0) ? &bt_s[0][0]
                                                          : &bi_s[0][0]);
            float a0 = 0.f, a1 = 0.f, a2 = 0.f, a3 = 0.f;
            #pragma unroll
            for (int ch = 0; ch < 4; ch++) {
                const int o = lane + 32 * ch;
                const float4 av = a4[o];
                const float4 c0 = cb[0 * 128 + o];
                const float4 c1 = cb[1 * 128 + o];
                const float4 c2 = cb[2 * 128 + o];
                const float4 c3 = cb[3 * 128 + o];
                a0 = fmaf(av.x, c0.x, fmaf(av.y, c0.y, fmaf(av.z, c0.z, fmaf(av.w, c0.w, a0))));
                a1 = fmaf(av.x, c1.x, fmaf(av.y, c1.y, fmaf(av.z, c1.z, fmaf(av.w, c1.w, a1))));
                a2 = fmaf(av.x, c2.x, fmaf(av.y, c2.y, fmaf(av.z, c2.z, fmaf(av.w, c2.w, a2))));
                a3 = fmaf(av.x, c3.x, fmaf(av.y, c3.y, fmaf(av.z, c3.z, fmaf(av.w, c3.w, a3))));
            }
            #pragma unroll
            for (int off = 16; off > 0; off >>= 1) {
                a0 += __shfl_down_sync(0xffffffffu, a0, off);
                a1 += __shfl_down_sync(0xffffffffu, a1, off);
                a2 += __shfl_down_sync(0xffffffffu, a2, off);
                a3 += __shfl_down_sync(0xffffffffu, a3, off);
            }
            if (lane == 0) {
                raw[mat][i][0] = a0; raw[mat][i][1] = a1;
                raw[mat][i][2] = a2; raw[mat][i][3] = a3;
            }
        }
    }
    __syncthreads();

    // ---- D (parallel): split-reduction (warps 0-2) + tiny graph (warp 7) ----
    if (tid < 32) {
        float s0 = 0.f, s1 = 0.f, s2 = 0.f, s3 = 0.f;
        #pragma unroll
        for (int s = 0; s < 64; s += 4) {
            s0 += pacc_tt[s][tid];     s1 += pacc_tt[s + 1][tid];
            s2 += pacc_tt[s + 2][tid]; s3 += pacc_tt[s + 3][tid];
        }
        sums[tid] = (s0 + s1) + (s2 + s3);
    } else if (tid < 96) {
        const int idx = tid - 32;
        float s0 = 0.f, s1 = 0.f, s2 = 0.f, s3 = 0.f;
        #pragma unroll
        for (int s = 0; s < 64; s += 4) {
            s0 += pacc_it[s][idx];     s1 += pacc_it[s + 1][idx];
            s2 += pacc_it[s + 2][idx]; s3 += pacc_it[s + 3][idx];
        }
        sums[32 + idx] = (s0 + s1) + (s2 + s3);
    } else if (tid >= 224 && tid < 232) {
        const int b = tid & 3;
        const bool is_it = (tid & 4) != 0;
        float rnt[NB], rni[NB];
        #pragma unroll
        for (int i = 0; i < NB; i++) {
            rnt[i] = rsqrtf(fmaxf(raw[0][i][i], 1e-24f));
            rni[i] = rsqrtf(fmaxf(raw[2][i][i], 1e-24f));
        }
        float e[5][5];
        if (!is_it) {
            e[0][0] = raw[0][b][b] * rnt[b] * rnt[b];
            #pragma unroll
            for (int m = 1; m < 5; m++) {
                e[0][m] = raw[0][b][m - 1] * rnt[b] * rnt[m - 1];
                e[m][0] = raw[0][m - 1][b] * rnt[m - 1] * rnt[b];
            }
            #pragma unroll
            for (int n = 1; n < 5; n++)
                #pragma unroll
                for (int m = 1; m < 5; m++)
                    e[n][m] = raw[0][n - 1][m - 1] * rnt[n - 1] * rnt[m - 1];
        } else {
            e[0][0] = raw[0][b][b] * rnt[b] * rnt[b];
            #pragma unroll
            for (int m = 1; m < 5; m++) {
                e[0][m] = raw[1][b][m - 1] * rnt[b] * rni[m - 1];
                e[m][0] = e[0][m];
            }
            #pragma unroll
            for (int n = 1; n < 5; n++)
                #pragma unroll
                for (int m = 1; m < 5; m++)
                    e[n][m] = raw[2][n - 1][m - 1] * rni[n - 1] * rni[m - 1];
        }
        float adj[5][5], deg[5];
        #pragma unroll
        for (int n = 0; n < 5; n++) {
            deg[n] = 0.f;
            #pragma unroll
            for (int m = 0; m < 5; m++) {
                adj[n][m] = fmaxf(e[n][m], 0.f) + ((n == m) ? 1.f : 0.f);
                deg[n] += adj[n][m];
            }
        }
        float dinv[5];
        #pragma unroll
        for (int n = 0; n < 5; n++)
            dinv[n] = rsqrtf(deg[n]);
        float* cc = is_it ? c_it[b] : c_tt[b];
        #pragma unroll
        for (int m = 0; m < 5; m++)
            cc[m] = dinv[0] * adj[0][m] * dinv[m];
    }
    __syncthreads();

    // ---- E: combine coefficients + bias + tanh + blend (32 threads) ----
    if (tid < 32) {
        const int col = tid & 7;
        const int b   = tid >> 3;
        const int g   = col >> 2, c = col & 3;
        const int d   = blockIdx.x * CPB + col;
        const int o   = g * 16 + c;

        float att = c_tt[b][0] * sums[o + b * 4];
        float ait = c_it[b][0] * sums[32 + o + b * 4];
        #pragma unroll
        for (int j = 0; j < 4; j++) {
            att = fmaf(c_tt[b][j + 1], sums[o + j * 4],      att);
            ait = fmaf(c_it[b][j + 1], sums[64 + o + j * 4], ait);
        }
        const float stt = att + btt[b * DD + d];
        const float sit = ait + bit_[b * DD + d];
        const float gg = ALPHA_IT * tanhf(stt) + (1.f - ALPHA_IT) * tanhf(sit);
        out[b * DD + d] = BETA_IT * bt_s[b][d] + (1.f - BETA_IT) * gg;
    }
}

extern "C" void kernel_launch(void* const* d_in, const int* in_sizes, int n_in,
                              void* d_out, int out_size) {
    const float* bt   = (const float*)d_in[0];
    const float* bi   = (const float*)d_in[1];
    const float* img  = (const float*)d_in[2];
    const float* Wtt  = (const float*)d_in[3];
    const float* btt  = (const float*)d_in[4];
    const float* Wit  = (const float*)d_in[5];
    const float* bit_ = (const float*)d_in[6];
    float* out = (float*)d_out;

    dim3 grid(NCOMP + NCOPY), block(TPB);   // 576 blocks, single wave @ 4/SM
    graphlearner_fused<<<grid, block>>>(bt, bi, img, Wtt, btt, Wit, bit_, out);
}

// round 10
// speedup vs baseline: 1.8759x; 1.0082x over previous
#include <cuda_runtime.h>
#include <math.h>

#define NB    4       // batch / classes
#define DD    512     // feature dim
#define TPB   256
#define NCOMP 64      // compute blocks (8 output columns each)
#define NCOPY 512     // dedicated copy blocks
#define CPB   8
#define COMP_SHARE 6144   // float4 copied by each compute block (3 x 8-deep)
#define ALPHA_IT 0.7f
#define BETA_IT  0.5f

// Deep-batched streaming copy of [start, end) float4, block-stride TPB.
__device__ __forceinline__ void copy_range(const float4* __restrict__ src,
                                           float4* __restrict__ dst,
                                           long long start, long long end,
                                           int tid)
{
    long long i = start + tid;
    #pragma unroll 1
    for (; i + 7 * TPB < end; i += 8 * TPB) {
        float4 a0 = src[i];
        float4 a1 = src[i + 1 * TPB];
        float4 a2 = src[i + 2 * TPB];
        float4 a3 = src[i + 3 * TPB];
        float4 a4 = src[i + 4 * TPB];
        float4 a5 = src[i + 5 * TPB];
        float4 a6 = src[i + 6 * TPB];
        float4 a7 = src[i + 7 * TPB];
        dst[i]           = a0;
        dst[i + 1 * TPB] = a1;
        dst[i + 2 * TPB] = a2;
        dst[i + 3 * TPB] = a3;
        dst[i + 4 * TPB] = a4;
        dst[i + 5 * TPB] = a5;
        dst[i + 6 * TPB] = a6;
        dst[i + 7 * TPB] = a7;
    }
    if (i + 3 * TPB < end) {
        float4 a0 = src[i];
        float4 a1 = src[i + 1 * TPB];
        float4 a2 = src[i + 2 * TPB];
        float4 a3 = src[i + 3 * TPB];
        dst[i]           = a0;
        dst[i + 1 * TPB] = a1;
        dst[i + 2 * TPB] = a2;
        dst[i + 3 * TPB] = a3;
        i += 4 * TPB;
    }
    if (i + TPB < end) {
        float4 a0 = src[i];
        float4 a1 = src[i + TPB];
        dst[i]       = a0;
        dst[i + TPB] = a1;
        i += 2 * TPB;
    }
    if (i < end)
        dst[i] = src[i];
}

// Fused single kernel, load-balanced:
//   blocks 0..63   : graph + dual GEMV -> refined, THEN copy COMP_SHARE f4
//   blocks 64..575 : stream their slice of img_feature -> out+2048
// 576 blocks, 4 blocks/SM, single wave on 148 SMs.
__global__ void __launch_bounds__(TPB, 4)
graphlearner_fused(const float* __restrict__ bt,    // (4,512)
                   const float* __restrict__ bi,    // (4,512)
                   const float* __restrict__ img,   // (40960,512)
                   const float* __restrict__ Wtt,   // (512,512)
                   const float* __restrict__ btt,   // (4,512)
                   const float* __restrict__ Wit,   // (512,512)
                   const float* __restrict__ bit_,  // (4,512)
                   float* __restrict__ out,
                   long long n_f4)
{
    const int tid = threadIdx.x;
    const float4* __restrict__ src = (const float4*)img;
    float4* __restrict__ dst = (float4*)(out + NB * DD);

    // copy-block share of the front region [0, base)
    const long long base = n_f4 - (long long)NCOMP * COMP_SHARE;
    const long long pshare = (base + NCOPY - 1) / NCOPY;

    // ---------------- dedicated copy blocks --------------------------------
    if (blockIdx.x >= NCOMP) {
        const long long start = (long long)(blockIdx.x - NCOMP) * pshare;
        long long end = start + pshare;
        if (end > base) end = base;
        copy_range(src, dst, start, end, tid);
        return;
    }

    // ---------------- compute blocks (verified R8/R9 path) -----------------
    const int warp = tid >> 5, lane = tid & 31;

    __shared__ float bt_s[NB][DD];                       // 8 KB
    __shared__ float bi_s[NB][DD];                       // 8 KB
    __shared__ __align__(16) float pacc_tt[64][32];      // 8 KB
    __shared__ __align__(16) float pacc_it[64][64];      // 16 KB
    __shared__ float raw[3][NB][NB];
    __shared__ float c_tt[NB][5], c_it[NB][5];
    __shared__ float sums[96];

    // ---- A: load features (float4) ----
    {
        const float4* bt4 = (const float4*)bt;
        const float4* bi4 = (const float4*)bi;
        #pragma unroll
        for (int i = tid; i < NB * DD / 4; i += TPB) {
            ((float4*)bt_s)[i] = bt4[i];
            ((float4*)bi_s)[i] = bi4[i];
        }
    }
    __syncthreads();

    // ---- B: per-node GEMV partials ----
    {
        const int g   = tid & 1;
        const int s   = (tid >> 1) & 63;
        const int mat = tid >> 7;
        const int d0  = blockIdx.x * CPB + g * 4;
        const float* __restrict__ W = mat ? Wit : Wtt;

        float4 accB[NB], accI[NB];
        #pragma unroll
        for (int m = 0; m < NB; m++) {
            accB[m] = make_float4(0.f, 0.f, 0.f, 0.f);
            accI[m] = make_float4(0.f, 0.f, 0.f, 0.f);
        }
        #pragma unroll
        for (int kk = 0; kk < 8; kk++) {
            const int k = kk * 64 + s;
            const float4 w = *(const float4*)(W + (size_t)k * DD + d0);
            #pragma unroll
            for (int m = 0; m < NB; m++) {
                const float bm = bt_s[m][k];
                accB[m].x = fmaf(bm, w.x, accB[m].x);
                accB[m].y = fmaf(bm, w.y, accB[m].y);
                accB[m].z = fmaf(bm, w.z, accB[m].z);
                accB[m].w = fmaf(bm, w.w, accB[m].w);
            }
            if (mat) {
                #pragma unroll
                for (int m = 0; m < NB; m++) {
                    const float im = bi_s[m][k];
                    accI[m].x = fmaf(im, w.x, accI[m].x);
                    accI[m].y = fmaf(im, w.y, accI[m].y);
                    accI[m].z = fmaf(im, w.z, accI[m].z);
                    accI[m].w = fmaf(im, w.w, accI[m].w);
                }
            }
        }
        if (mat == 0) {
            float4* row = (float4*)&pacc_tt[s][g * 16];
            #pragma unroll
            for (int m = 0; m < NB; m++) row[m] = accB[m];
        } else {
            float4* rowB = (float4*)&pacc_it[s][g * 16];
            float4* rowI = (float4*)&pacc_it[s][32 + g * 16];
            #pragma unroll
            for (int m = 0; m < NB; m++) { rowB[m] = accB[m]; rowI[m] = accI[m]; }
        }
    }

    // ---- C: gram dots, batched 4 per warp-pass ----
    {
        #pragma unroll
        for (int pass = 0; pass < 2; pass++) {
            if (pass == 1 && warp >= 4) break;
            const int G   = (pass == 0) ? warp : 8 + warp;
            const int mat = G >> 2, i = G & 3;
            const float4* a4 = (const float4*)((mat == 2) ? bi_s[i] : bt_s[i]);
            const float4* cb = (const float4*)((mat == 0) ? &bt_s[0][0]
                                                          : &bi_s[0][0]);
            float a0 = 0.f, a1 = 0.f, a2 = 0.f, a3 = 0.f;
            #pragma unroll
            for (int ch = 0; ch < 4; ch++) {
                const int o = lane + 32 * ch;
                const float4 av = a4[o];
                const float4 c0 = cb[0 * 128 + o];
                const float4 c1 = cb[1 * 128 + o];
                const float4 c2 = cb[2 * 128 + o];
                const float4 c3 = cb[3 * 128 + o];
                a0 = fmaf(av.x, c0.x, fmaf(av.y, c0.y, fmaf(av.z, c0.z, fmaf(av.w, c0.w, a0))));
                a1 = fmaf(av.x, c1.x, fmaf(av.y, c1.y, fmaf(av.z, c1.z, fmaf(av.w, c1.w, a1))));
                a2 = fmaf(av.x, c2.x, fmaf(av.y, c2.y, fmaf(av.z, c2.z, fmaf(av.w, c2.w, a2))));
                a3 = fmaf(av.x, c3.x, fmaf(av.y, c3.y, fmaf(av.z, c3.z, fmaf(av.w, c3.w, a3))));
            }
            #pragma unroll
            for (int off = 16; off > 0; off >>= 1) {
                a0 += __shfl_down_sync(0xffffffffu, a0, off);
                a1 += __shfl_down_sync(0xffffffffu, a1, off);
                a2 += __shfl_down_sync(0xffffffffu, a2, off);
                a3 += __shfl_down_sync(0xffffffffu, a3, off);
            }
            if (lane == 0) {
                raw[mat][i][0] = a0; raw[mat][i][1] = a1;
                raw[mat][i][2] = a2; raw[mat][i][3] = a3;
            }
        }
    }
    __syncthreads();

    // ---- D (parallel): split-reduction + tiny graph ----
    if (tid < 32) {
        float s0 = 0.f, s1 = 0.f, s2 = 0.f, s3 = 0.f;
        #pragma unroll
        for (int s = 0; s < 64; s += 4) {
            s0 += pacc_tt[s][tid];     s1 += pacc_tt[s + 1][tid];
            s2 += pacc_tt[s + 2][tid]; s3 += pacc_tt[s + 3][tid];
        }
        sums[tid] = (s0 + s1) + (s2 + s3);
    } else if (tid < 96) {
        const int idx = tid - 32;
        float s0 = 0.f, s1 = 0.f, s2 = 0.f, s3 = 0.f;
        #pragma unroll
        for (int s = 0; s < 64; s += 4) {
            s0 += pacc_it[s][idx];     s1 += pacc_it[s + 1][idx];
            s2 += pacc_it[s + 2][idx]; s3 += pacc_it[s + 3][idx];
        }
        sums[32 + idx] = (s0 + s1) + (s2 + s3);
    } else if (tid >= 224 && tid < 232) {
        const int b = tid & 3;
        const bool is_it = (tid & 4) != 0;
        float rnt[NB], rni[NB];
        #pragma unroll
        for (int i = 0; i < NB; i++) {
            rnt[i] = rsqrtf(fmaxf(raw[0][i][i], 1e-24f));
            rni[i] = rsqrtf(fmaxf(raw[2][i][i], 1e-24f));
        }
        float e[5][5];
        if (!is_it) {
            e[0][0] = raw[0][b][b] * rnt[b] * rnt[b];
            #pragma unroll
            for (int m = 1; m < 5; m++) {
                e[0][m] = raw[0][b][m - 1] * rnt[b] * rnt[m - 1];
                e[m][0] = raw[0][m - 1][b] * rnt[m - 1] * rnt[b];
            }
            #pragma unroll
            for (int n = 1; n < 5; n++)
                #pragma unroll
                for (int m = 1; m < 5; m++)
                    e[n][m] = raw[0][n - 1][m - 1] * rnt[n - 1] * rnt[m - 1];
        } else {
            e[0][0] = raw[0][b][b] * rnt[b] * rnt[b];
            #pragma unroll
            for (int m = 1; m < 5; m++) {
                e[0][m] = raw[1][b][m - 1] * rnt[b] * rni[m - 1];
                e[m][0] = e[0][m];
            }
            #pragma unroll
            for (int n = 1; n < 5; n++)
                #pragma unroll
                for (int m = 1; m < 5; m++)
                    e[n][m] = raw[2][n - 1][m - 1] * rni[n - 1] * rni[m - 1];
        }
        float adj[5][5], deg[5];
        #pragma unroll
        for (int n = 0; n < 5; n++) {
            deg[n] = 0.f;
            #pragma unroll
            for (int m = 0; m < 5; m++) {
                adj[n][m] = fmaxf(e[n][m], 0.f) + ((n == m) ? 1.f : 0.f);
                deg[n] += adj[n][m];
            }
        }
        float dinv[5];
        #pragma unroll
        for (int n = 0; n < 5; n++)
            dinv[n] = rsqrtf(deg[n]);
        float* cc = is_it ? c_it[b] : c_tt[b];
        #pragma unroll
        for (int m = 0; m < 5; m++)
            cc[m] = dinv[0] * adj[0][m] * dinv[m];
    }
    __syncthreads();

    // ---- E: combine + bias + tanh + blend (32 threads) ----
    if (tid < 32) {
        const int col = tid & 7;
        const int b   = tid >> 3;
        const int g   = col >> 2, c = col & 3;
        const int d   = blockIdx.x * CPB + col;
        const int o   = g * 16 + c;

        float att = c_tt[b][0] * sums[o + b * 4];
        float ait = c_it[b][0] * sums[32 + o + b * 4];
        #pragma unroll
        for (int j = 0; j < 4; j++) {
            att = fmaf(c_tt[b][j + 1], sums[o + j * 4],      att);
            ait = fmaf(c_it[b][j + 1], sums[64 + o + j * 4], ait);
        }
        const float stt = att + btt[b * DD + d];
        const float sit = ait + bit_[b * DD + d];
        const float gg = ALPHA_IT * tanhf(stt) + (1.f - ALPHA_IT) * tanhf(sit);
        out[b * DD + d] = BETA_IT * bt_s[b][d] + (1.f - BETA_IT) * gg;
    }

    // ---- F: join the copy — tail region [base, n_f4) ----
    {
        const long long start = base + (long long)blockIdx.x * COMP_SHARE;
        copy_range(src, dst, start, start + COMP_SHARE, tid);
    }
}

extern "C" void kernel_launch(void* const* d_in, const int* in_sizes, int n_in,
                              void* d_out, int out_size) {
    const float* bt   = (const float*)d_in[0];
    const float* bi   = (const float*)d_in[1];
    const float* img  = (const float*)d_in[2];
    const float* Wtt  = (const float*)d_in[3];
    const float* btt  = (const float*)d_in[4];
    const float* Wit  = (const float*)d_in[5];
    const float* bit_ = (const float*)d_in[6];
    float* out = (float*)d_out;

    const long long n_f4 = (long long)in_sizes[2] / 4;   // 5,242,880

    dim3 grid(NCOMP + NCOPY), block(TPB);   // 576 blocks, single wave @ 4/SM
    graphlearner_fused<<<grid, block>>>(bt, bi, img, Wtt, btt, Wit, bit_,
                                        out, n_f4);
}